// round 1
// baseline (speedup 1.0000x reference)
#include <cuda_runtime.h>
#include <math.h>

#define N_EL 4096
#define N_NB 32
#define F_IN 5
#define EDGE_FEAT 32
#define FEAT 256
#define CUTOFF_F 3.0f

__global__ __launch_bounds__(256, 2)
void edge_features_kernel(
    const float* __restrict__ r,        // [N,3]
    const float* __restrict__ r_nb,     // [N,K,3]
    const float* __restrict__ fkern,    // [N,5,32]
    const float* __restrict__ fbias,    // [N,32]
    const float* __restrict__ Wg,       // [32,256]
    const float* __restrict__ ekern,    // [N,5,256]
    const float* __restrict__ ebias,    // [N,256]
    const int*   __restrict__ s,        // [N]
    const int*   __restrict__ s_nb,     // [N,K]
    float*       __restrict__ out)      // [2, N, K, 256]
{
    const int n   = blockIdx.x;
    const int tid = threadIdx.x;

    __shared__ __align__(16) float sh_feats[N_NB][F_IN];    // 32x5
    __shared__ __align__(16) float sh_env[N_NB];            // 32
    __shared__ __align__(16) float sh_fk[F_IN][EDGE_FEAT];  // 5x32
    __shared__ __align__(16) float sh_fb[EDGE_FEAT];        // 32
    __shared__ __align__(16) float sh_fkW[F_IN][FEAT];      // 5x256
    __shared__ __align__(16) float sh_fbW[FEAT];            // 256

    // ---- stage per-n filter params ----
    if (tid < F_IN * EDGE_FEAT) {
        sh_fk[tid / EDGE_FEAT][tid % EDGE_FEAT] = fkern[(size_t)n * F_IN * EDGE_FEAT + tid];
    } else if (tid < F_IN * EDGE_FEAT + EDGE_FEAT) {
        int e = tid - F_IN * EDGE_FEAT;
        sh_fb[e] = fbias[(size_t)n * EDGE_FEAT + e];
    }

    // ---- geometric features + cutoff envelope (32 threads) ----
    if (tid < N_NB) {
        int k = tid;
        float rx = r[n * 3 + 0], ry = r[n * 3 + 1], rz = r[n * 3 + 2];
        const float* rn = &r_nb[((size_t)n * N_NB + k) * 3];
        float dx = rn[0] - rx, dy = rn[1] - ry, dz = rn[2] - rz;
        float dist = sqrtf(dx * dx + dy * dy + dz * dz);
        sh_feats[k][0] = dx;
        sh_feats[k][1] = dy;
        sh_feats[k][2] = dz;
        sh_feats[k][3] = dist;
        sh_feats[k][4] = (s[n] == s_nb[(size_t)n * N_NB + k]) ? 1.0f : 0.0f;
        float env = 0.0f;
        if (dist < CUTOFF_F) {
            float x = dist * (1.0f / CUTOFF_F);
            if (x > 1.0f) x = 1.0f;
            env = 0.5f * (cospif(x) + 1.0f);
        }
        sh_env[k] = env;
    }
    __syncthreads();

    // ---- cooperative FkW = Fk @ Wg, fbW = fb @ Wg  (one d-column per thread) ----
    {
        const int d = tid;
        float a0 = 0.f, a1 = 0.f, a2 = 0.f, a3 = 0.f, a4 = 0.f, ab = 0.f;
#pragma unroll
        for (int e = 0; e < EDGE_FEAT; e++) {
            float w = Wg[e * FEAT + d];     // coalesced, L1/L2-resident (32 KB total)
            ab += sh_fb[e] * w;
            a0 += sh_fk[0][e] * w;
            a1 += sh_fk[1][e] * w;
            a2 += sh_fk[2][e] * w;
            a3 += sh_fk[3][e] * w;
            a4 += sh_fk[4][e] * w;
        }
        sh_fkW[0][d] = a0; sh_fkW[1][d] = a1; sh_fkW[2][d] = a2;
        sh_fkW[3][d] = a3; sh_fkW[4][d] = a4; sh_fbW[d] = ab;
    }
    __syncthreads();

    // ---- main: tid -> (4 consecutive d, 8 k); float4 everywhere ----
    const int dg = tid & 63;      // 0..63
    const int kq = tid >> 6;      // 0..3
    const int d0 = dg * 4;

    float4 gk0 = *(const float4*)&sh_fkW[0][d0];
    float4 gk1 = *(const float4*)&sh_fkW[1][d0];
    float4 gk2 = *(const float4*)&sh_fkW[2][d0];
    float4 gk3 = *(const float4*)&sh_fkW[3][d0];
    float4 gk4 = *(const float4*)&sh_fkW[4][d0];
    float4 gb  = *(const float4*)&sh_fbW[d0];

    const float* ek_base = &ekern[(size_t)n * F_IN * FEAT + d0];
    float4 ek0 = *(const float4*)&ek_base[0 * FEAT];
    float4 ek1 = *(const float4*)&ek_base[1 * FEAT];
    float4 ek2 = *(const float4*)&ek_base[2 * FEAT];
    float4 ek3 = *(const float4*)&ek_base[3 * FEAT];
    float4 ek4 = *(const float4*)&ek_base[4 * FEAT];
    float4 eb  = *(const float4*)&ebias[(size_t)n * FEAT + d0];

    const size_t gbase = (size_t)n * N_NB * FEAT;
    const size_t EOFF  = (size_t)N_EL * N_NB * FEAT;

#pragma unroll
    for (int kk = 0; kk < 8; kk++) {
        const int k = kq * 8 + kk;
        const float f0 = sh_feats[k][0];
        const float f1 = sh_feats[k][1];
        const float f2 = sh_feats[k][2];
        const float f3 = sh_feats[k][3];
        const float f4 = sh_feats[k][4];
        const float env = sh_env[k];

        float4 g, e;
        g.x = env * (gb.x + f0 * gk0.x + f1 * gk1.x + f2 * gk2.x + f3 * gk3.x + f4 * gk4.x);
        g.y = env * (gb.y + f0 * gk0.y + f1 * gk1.y + f2 * gk2.y + f3 * gk3.y + f4 * gk4.y);
        g.z = env * (gb.z + f0 * gk0.z + f1 * gk1.z + f2 * gk2.z + f3 * gk3.z + f4 * gk4.z);
        g.w = env * (gb.w + f0 * gk0.w + f1 * gk1.w + f2 * gk2.w + f3 * gk3.w + f4 * gk4.w);

        e.x = eb.x + f0 * ek0.x + f1 * ek1.x + f2 * ek2.x + f3 * ek3.x + f4 * ek4.x;
        e.y = eb.y + f0 * ek0.y + f1 * ek1.y + f2 * ek2.y + f3 * ek3.y + f4 * ek4.y;
        e.z = eb.z + f0 * ek0.z + f1 * ek1.z + f2 * ek2.z + f3 * ek3.z + f4 * ek4.z;
        e.w = eb.w + f0 * ek0.w + f1 * ek1.w + f2 * ek2.w + f3 * ek3.w + f4 * ek4.w;

        const size_t o = gbase + (size_t)k * FEAT + d0;
        *(float4*)&out[o]        = g;   // Gamma
        *(float4*)&out[EOFF + o] = e;   // edge_features
    }
}

extern "C" void kernel_launch(void* const* d_in, const int* in_sizes, int n_in,
                              void* d_out, int out_size) {
    const float* r     = (const float*)d_in[0];
    const float* r_nb  = (const float*)d_in[1];
    const float* fkern = (const float*)d_in[2];
    const float* fbias = (const float*)d_in[3];
    const float* Wg    = (const float*)d_in[4];
    const float* ekern = (const float*)d_in[5];
    const float* ebias = (const float*)d_in[6];
    const int*   s     = (const int*)d_in[7];
    const int*   s_nb  = (const int*)d_in[8];
    float* out = (float*)d_out;

    edge_features_kernel<<<N_EL, 256>>>(r, r_nb, fkern, fbias, Wg, ekern, ebias, s, s_nb, out);
}

// round 2
// speedup vs baseline: 1.3630x; 1.3630x over previous
#include <cuda_runtime.h>
#include <math.h>

#define N_EL 4096
#define N_NB 32
#define F_IN 5
#define EDGE_FEAT 32
#define FEAT 256
#define CUTOFF_F 3.0f

__global__ __launch_bounds__(512, 2)
void edge_features_kernel(
    const float* __restrict__ r,        // [N,3]
    const float* __restrict__ r_nb,     // [N,K,3]
    const float* __restrict__ fkern,    // [N,5,32]
    const float* __restrict__ fbias,    // [N,32]
    const float* __restrict__ Wg,       // [32,256]
    const float* __restrict__ ekern,    // [N,5,256]
    const float* __restrict__ ebias,    // [N,256]
    const int*   __restrict__ s,        // [N]
    const int*   __restrict__ s_nb,     // [N,K]
    float*       __restrict__ out)      // [2, N, K, 256]
{
    const int n   = blockIdx.x;
    const int tid = threadIdx.x;

    __shared__ __align__(16) float sh_feats[N_NB][F_IN];    // 32x5
    __shared__ __align__(16) float sh_env[N_NB];            // 32
    __shared__ __align__(16) float sh_fk[F_IN][EDGE_FEAT];  // 5x32
    __shared__ __align__(16) float sh_fb[EDGE_FEAT];        // 32
    __shared__ __align__(16) float sh_fkW[F_IN][FEAT];      // 5x256
    __shared__ __align__(16) float sh_fbW[FEAT];            // 256

    // ---- stage per-n filter params (first 192 threads) ----
    if (tid < F_IN * EDGE_FEAT) {
        sh_fk[tid / EDGE_FEAT][tid % EDGE_FEAT] = fkern[(size_t)n * F_IN * EDGE_FEAT + tid];
    } else if (tid < F_IN * EDGE_FEAT + EDGE_FEAT) {
        int e = tid - F_IN * EDGE_FEAT;
        sh_fb[e] = fbias[(size_t)n * EDGE_FEAT + e];
    }

    // ---- geometric features + cutoff envelope (warps 8..8: tid 256..287) ----
    if (tid >= 256 && tid < 256 + N_NB) {
        int k = tid - 256;
        float rx = r[n * 3 + 0], ry = r[n * 3 + 1], rz = r[n * 3 + 2];
        const float* rn = &r_nb[((size_t)n * N_NB + k) * 3];
        float dx = rn[0] - rx, dy = rn[1] - ry, dz = rn[2] - rz;
        float dist = sqrtf(dx * dx + dy * dy + dz * dz);
        sh_feats[k][0] = dx;
        sh_feats[k][1] = dy;
        sh_feats[k][2] = dz;
        sh_feats[k][3] = dist;
        sh_feats[k][4] = (s[n] == s_nb[(size_t)n * N_NB + k]) ? 1.0f : 0.0f;
        float env = 0.0f;
        if (dist < CUTOFF_F) {
            float x = dist * (1.0f / CUTOFF_F);
            if (x > 1.0f) x = 1.0f;
            env = 0.5f * (cospif(x) + 1.0f);
        }
        sh_env[k] = env;
    }
    __syncthreads();

    // ---- cooperative FkW = Fk @ Wg, fbW = fb @ Wg (threads 0..255, one d each) ----
    if (tid < FEAT) {
        const int d = tid;
        float a0 = 0.f, a1 = 0.f, a2 = 0.f, a3 = 0.f, a4 = 0.f, ab = 0.f;
#pragma unroll
        for (int e = 0; e < EDGE_FEAT; e++) {
            float w = Wg[e * FEAT + d];     // coalesced, L2-resident (32 KB total)
            ab += sh_fb[e] * w;
            a0 += sh_fk[0][e] * w;
            a1 += sh_fk[1][e] * w;
            a2 += sh_fk[2][e] * w;
            a3 += sh_fk[3][e] * w;
            a4 += sh_fk[4][e] * w;
        }
        sh_fkW[0][d] = a0; sh_fkW[1][d] = a1; sh_fkW[2][d] = a2;
        sh_fkW[3][d] = a3; sh_fkW[4][d] = a4; sh_fbW[d] = ab;
    }
    __syncthreads();

    // ---- role split: tid<256 -> Gamma, tid>=256 -> edge_features ----
    const int t   = tid & 255;
    const int dg  = t & 63;       // 0..63  (varies within warp -> coalesced)
    const int kq  = t >> 6;       // 0..3   (uniform within warp -> feats broadcast)
    const int d0  = dg * 4;

    const size_t gbase = (size_t)n * N_NB * FEAT;
    const size_t EOFF  = (size_t)N_EL * N_NB * FEAT;

    if (tid < 256) {
        // ---- Gamma path: 6 float4 coefficients in regs ----
        float4 gk0 = *(const float4*)&sh_fkW[0][d0];
        float4 gk1 = *(const float4*)&sh_fkW[1][d0];
        float4 gk2 = *(const float4*)&sh_fkW[2][d0];
        float4 gk3 = *(const float4*)&sh_fkW[3][d0];
        float4 gk4 = *(const float4*)&sh_fkW[4][d0];
        float4 gb  = *(const float4*)&sh_fbW[d0];

#pragma unroll
        for (int kk = 0; kk < 8; kk++) {
            const int k = kq * 8 + kk;
            const float env = sh_env[k];
            const float f0 = env * sh_feats[k][0];
            const float f1 = env * sh_feats[k][1];
            const float f2 = env * sh_feats[k][2];
            const float f3 = env * sh_feats[k][3];
            const float f4 = env * sh_feats[k][4];

            float4 g;
            g.x = env * gb.x + f0 * gk0.x + f1 * gk1.x + f2 * gk2.x + f3 * gk3.x + f4 * gk4.x;
            g.y = env * gb.y + f0 * gk0.y + f1 * gk1.y + f2 * gk2.y + f3 * gk3.y + f4 * gk4.y;
            g.z = env * gb.z + f0 * gk0.z + f1 * gk1.z + f2 * gk2.z + f3 * gk3.z + f4 * gk4.z;
            g.w = env * gb.w + f0 * gk0.w + f1 * gk1.w + f2 * gk2.w + f3 * gk3.w + f4 * gk4.w;

            __stcs((float4*)&out[gbase + (size_t)k * FEAT + d0], g);
        }
    } else {
        // ---- edge path: 6 float4 coefficients in regs ----
        const float* ek_base = &ekern[(size_t)n * F_IN * FEAT + d0];
        float4 ek0 = *(const float4*)&ek_base[0 * FEAT];
        float4 ek1 = *(const float4*)&ek_base[1 * FEAT];
        float4 ek2 = *(const float4*)&ek_base[2 * FEAT];
        float4 ek3 = *(const float4*)&ek_base[3 * FEAT];
        float4 ek4 = *(const float4*)&ek_base[4 * FEAT];
        float4 eb  = *(const float4*)&ebias[(size_t)n * FEAT + d0];

#pragma unroll
        for (int kk = 0; kk < 8; kk++) {
            const int k = kq * 8 + kk;
            const float f0 = sh_feats[k][0];
            const float f1 = sh_feats[k][1];
            const float f2 = sh_feats[k][2];
            const float f3 = sh_feats[k][3];
            const float f4 = sh_feats[k][4];

            float4 e;
            e.x = eb.x + f0 * ek0.x + f1 * ek1.x + f2 * ek2.x + f3 * ek3.x + f4 * ek4.x;
            e.y = eb.y + f0 * ek0.y + f1 * ek1.y + f2 * ek2.y + f3 * ek3.y + f4 * ek4.y;
            e.z = eb.z + f0 * ek0.z + f1 * ek1.z + f2 * ek2.z + f3 * ek3.z + f4 * ek4.z;
            e.w = eb.w + f0 * ek0.w + f1 * ek1.w + f2 * ek2.w + f3 * ek3.w + f4 * ek4.w;

            __stcs((float4*)&out[EOFF + gbase + (size_t)k * FEAT + d0], e);
        }
    }
}

extern "C" void kernel_launch(void* const* d_in, const int* in_sizes, int n_in,
                              void* d_out, int out_size) {
    const float* r     = (const float*)d_in[0];
    const float* r_nb  = (const float*)d_in[1];
    const float* fkern = (const float*)d_in[2];
    const float* fbias = (const float*)d_in[3];
    const float* Wg    = (const float*)d_in[4];
    const float* ekern = (const float*)d_in[5];
    const float* ebias = (const float*)d_in[6];
    const int*   s     = (const int*)d_in[7];
    const int*   s_nb  = (const int*)d_in[8];
    float* out = (float*)d_out;

    edge_features_kernel<<<N_EL, 512>>>(r, r_nb, fkern, fbias, Wg, ekern, ebias, s, s_nb, out);
}